// round 9
// baseline (speedup 1.0000x reference)
#include <cuda_runtime.h>
#include <cuda_fp16.h>
#include <cstdint>

#define NN 50000
#define NE 200000
#define DD 128
#define RR 4
#define HH 64
#define NSM 152

__device__ float g_acc[NN * HH];
__device__ int   g_bucket[RR * NE];
__device__ int   g_cnt[RR];

__global__ void bin_kernel(const int* __restrict__ etype) {
    __shared__ int s_cnt[RR];
    __shared__ int s_base[RR];
    int t = threadIdx.x;
    if (t < RR) s_cnt[t] = 0;
    __syncthreads();
    int e = blockIdx.x * blockDim.x + t;
    int r = -1, pos = 0;
    if (e < NE) { r = etype[e]; pos = atomicAdd(&s_cnt[r], 1); }
    __syncthreads();
    if (t < RR) s_base[t] = atomicAdd(&g_cnt[t], s_cnt[t]);
    __syncthreads();
    if (r >= 0) g_bucket[r * NE + s_base[r] + pos] = e;
}

// ---- helpers ----------------------------------------------------------------
__device__ __forceinline__ void mma_f16(float c[4], uint32_t a0, uint32_t a1,
                                        uint32_t a2, uint32_t a3,
                                        uint32_t b0, uint32_t b1) {
    asm volatile(
        "mma.sync.aligned.m16n8k16.row.col.f32.f16.f16.f32 "
        "{%0,%1,%2,%3}, {%4,%5,%6,%7}, {%8,%9}, {%0,%1,%2,%3};"
        : "+f"(c[0]), "+f"(c[1]), "+f"(c[2]), "+f"(c[3])
        : "r"(a0), "r"(a1), "r"(a2), "r"(a3), "r"(b0), "r"(b1));
}
// pack two f32 -> f16x2 (low = lo, high = hi)
__device__ __forceinline__ uint32_t pack_h2(float lo, float hi) {
    uint32_t r;
    asm("cvt.rn.f16x2.f32 %0, %1, %2;" : "=r"(r) : "f"(hi), "f"(lo));
    return r;
}
__device__ __forceinline__ void red2(float* p, float x, float y) {
    asm volatile("red.global.add.v2.f32 [%0], {%1, %2};"
                 :: "l"(p), "f"(x), "f"(y) : "memory");
}

// Layer GEMM on register A fragments. A[kb][4] covers k = 16kb..16kb+15 for the
// warp's 16 rows; wT is [N][KS] f16 (K contiguous); C chunks j cover cols 8j..8j+7.
template<int KB, int NCH, int KS>
__device__ __forceinline__ void do_layer(const uint32_t A[][4],
                                         const __half* __restrict__ wT,
                                         int g, int tig, float c[][4]) {
    #pragma unroll
    for (int kb = 0; kb < KB; kb++) {
        #pragma unroll
        for (int j = 0; j < NCH; j++) {
            const __half* wn = wT + (8 * j + g) * KS + kb * 16 + 2 * tig;
            mma_f16(c[j], A[kb][0], A[kb][1], A[kb][2], A[kb][3],
                    *(const uint32_t*)wn, *(const uint32_t*)(wn + 8));
        }
    }
}

// bias + relu + repack C chunks (2 per k-block) into next-layer A fragments.
template<int KB2>
__device__ __forceinline__ void cvt_relu(const float c[][4],
                                         const float* __restrict__ bias,
                                         int tig, uint32_t A[][4]) {
    #pragma unroll
    for (int kb = 0; kb < KB2; kb++) {
        int j0 = 2 * kb, j1 = j0 + 1;
        float2 b0 = *(const float2*)(bias + 8 * j0 + 2 * tig);
        float2 b1 = *(const float2*)(bias + 8 * j1 + 2 * tig);
        A[kb][0] = pack_h2(fmaxf(c[j0][0] + b0.x, 0.f), fmaxf(c[j0][1] + b0.y, 0.f));
        A[kb][1] = pack_h2(fmaxf(c[j0][2] + b0.x, 0.f), fmaxf(c[j0][3] + b0.y, 0.f));
        A[kb][2] = pack_h2(fmaxf(c[j1][0] + b1.x, 0.f), fmaxf(c[j1][1] + b1.y, 0.f));
        A[kb][3] = pack_h2(fmaxf(c[j1][2] + b1.x, 0.f), fmaxf(c[j1][3] + b1.y, 0.f));
    }
}

// SMEM layouts (byte offsets). Weight rows stride: 136 halves (K=128), 72 (K=64)
// -> B-fragment LDS conflict-free (4g+tig bank pattern).
#define E_W1 0
#define E_W2 17408
#define E_W3 26624
#define E_WN 45056
#define E_B1 62464
#define E_B2 62720
#define E_B3 62976
#define E_STG 63488        /* 8 warps x 16 rows x 136 halves */
#define E_TOT 98304

#define N_W1 0
#define N_W2 17408
#define N_W3 26624
#define N_B1 45056
#define N_B2 45312
#define N_B3 45568
#define N_STG 46080
#define N_TOT 80896

// ---------------------------------------------------------------------------
// Edge kernel: each WARP independently processes 16 edges of its relation
// through all 4 layers; activations live in registers between layers.
// ---------------------------------------------------------------------------
__global__ __launch_bounds__(256, 1)
void edge_kernel(const float* __restrict__ nf,
                 const int* __restrict__ esrc, const int* __restrict__ edst,
                 const float* __restrict__ Wr1, const float* __restrict__ br1,
                 const float* __restrict__ Wr2, const float* __restrict__ br2,
                 const float* __restrict__ Wr3, const float* __restrict__ br3,
                 const float* __restrict__ Wn1) {
    extern __shared__ __align__(16) char sm[];
    __half* sW1 = (__half*)(sm + E_W1);   // [64][136]  W1^T
    __half* sW2 = (__half*)(sm + E_W2);   // [64][72]
    __half* sW3 = (__half*)(sm + E_W3);   // [128][72]
    __half* sWn = (__half*)(sm + E_WN);   // [64][136]
    float*  b1  = (float*)(sm + E_B1);
    float*  b2  = (float*)(sm + E_B2);
    float*  b3  = (float*)(sm + E_B3);

    const int t = threadIdx.x;
    const int rel = blockIdx.x & (RR - 1);

    const float* gW1 = Wr1 + rel * DD * HH;
    const float* gW2 = Wr2 + rel * HH * HH;
    const float* gW3 = Wr3 + rel * HH * DD;
    const float* gWn = Wn1 + (1 + rel) * DD * HH;
    for (int i = t; i < DD * HH; i += 256) {
        int d = i >> 6, h = i & 63;
        sW1[h * 136 + d] = __float2half(gW1[i]);
        sWn[h * 136 + d] = __float2half(gWn[i]);
    }
    for (int i = t; i < HH * HH; i += 256) {
        int k = i >> 6, h = i & 63;
        sW2[h * 72 + k] = __float2half(gW2[i]);
    }
    for (int i = t; i < HH * DD; i += 256) {
        int k = i >> 7, d = i & 127;
        sW3[d * 72 + k] = __float2half(gW3[i]);
    }
    if (t < HH) { b1[t] = br1[rel * HH + t]; b2[t] = br2[rel * HH + t]; }
    if (t < DD) { b3[t] = br3[rel * DD + t]; }
    __syncthreads();

    const int lane = t & 31, wid = t >> 5;
    const int g = lane >> 2, tig = lane & 3;
    __half* stage = (__half*)(sm + E_STG) + wid * (16 * 136);
    const int srow = lane >> 1, shalf = lane & 1;    // 2 lanes gather one row

    const int cnt = g_cnt[rel];
    const int nunits = (cnt + 15) >> 4;
    const int slot0 = (blockIdx.x >> 2) * 8 + wid;
    const int nslots = (gridDim.x >> 2) * 8;

    for (int u = slot0; u < nunits; u += nslots) {
        int s = 0, d = -1;
        if (lane < 16) {
            int idx = u * 16 + lane;
            if (idx < cnt) {
                int e = g_bucket[rel * NE + idx];
                s = esrc[e]; d = edst[e];
            }
        }
        int src_r = __shfl_sync(0xffffffffu, s, srow);
        int d0 = __shfl_sync(0xffffffffu, d, g);
        int d1 = __shfl_sync(0xffffffffu, d, g + 8);

        // stage x_src[16 rows][128] as f16
        {
            const float* xr = nf + (long)src_r * DD + shalf * 64;
            __half* dr = stage + srow * 136 + shalf * 64;
            #pragma unroll
            for (int i = 0; i < 16; i++) {
                float4 v = *(const float4*)(xr + 4 * i);
                uint2 hp; hp.x = pack_h2(v.x, v.y); hp.y = pack_h2(v.z, v.w);
                *(uint2*)(dr + 4 * i) = hp;
            }
        }
        __syncwarp();

        // L1: K=128, N=64 (A from staged x)
        float c1[8][4] = {};
        #pragma unroll
        for (int kb = 0; kb < 8; kb++) {
            const __half* ar = stage + g * 136 + kb * 16 + 2 * tig;
            uint32_t a0 = *(const uint32_t*)ar;
            uint32_t a1 = *(const uint32_t*)(ar + 8 * 136);
            uint32_t a2 = *(const uint32_t*)(ar + 8);
            uint32_t a3 = *(const uint32_t*)(ar + 8 * 136 + 8);
            #pragma unroll
            for (int j = 0; j < 8; j++) {
                const __half* wn = sW1 + (8 * j + g) * 136 + kb * 16 + 2 * tig;
                mma_f16(c1[j], a0, a1, a2, a3,
                        *(const uint32_t*)wn, *(const uint32_t*)(wn + 8));
            }
        }
        uint32_t A[8][4];
        cvt_relu<4>(c1, b1, tig, A);

        // L2: K=64, N=64
        float c2[8][4] = {};
        do_layer<4, 8, 72>(A, sW2, g, tig, c2);
        cvt_relu<4>(c2, b2, tig, A);

        // L3: K=64, N=128
        float c3[16][4] = {};
        do_layer<4, 16, 72>(A, sW3, g, tig, c3);
        cvt_relu<8>(c3, b3, tig, A);

        // L4: K=128, N=64 (fused node-layer-1 projection)
        float c4[8][4] = {};
        do_layer<8, 8, 136>(A, sWn, g, tig, c4);

        #pragma unroll
        for (int j = 0; j < 8; j++) {
            int col = 8 * j + 2 * tig;
            if (d0 >= 0) red2(g_acc + (long)d0 * HH + col, c4[j][0], c4[j][1]);
            if (d1 >= 0) red2(g_acc + (long)d1 * HH + col, c4[j][2], c4[j][3]);
        }
        __syncwarp();   // staging reuse
    }
}

// ---------------------------------------------------------------------------
// Node kernel: warp-independent 16-node units; g_acc fused into L1 epilogue.
// ---------------------------------------------------------------------------
__global__ __launch_bounds__(256, 1)
void node_kernel(const float* __restrict__ nf,
                 const float* __restrict__ Wn1, const float* __restrict__ bn1,
                 const float* __restrict__ Wn2, const float* __restrict__ bn2,
                 const float* __restrict__ Wn3, const float* __restrict__ bn3,
                 float* __restrict__ out) {
    extern __shared__ __align__(16) char sm[];
    __half* sW1 = (__half*)(sm + N_W1);
    __half* sW2 = (__half*)(sm + N_W2);
    __half* sW3 = (__half*)(sm + N_W3);
    float*  b1  = (float*)(sm + N_B1);
    float*  b2  = (float*)(sm + N_B2);
    float*  b3  = (float*)(sm + N_B3);

    const int t = threadIdx.x;
    for (int i = t; i < DD * HH; i += 256) {
        int d = i >> 6, h = i & 63;
        sW1[h * 136 + d] = __float2half(Wn1[i]);
    }
    for (int i = t; i < HH * HH; i += 256) {
        int k = i >> 6, h = i & 63;
        sW2[h * 72 + k] = __float2half(Wn2[i]);
    }
    for (int i = t; i < HH * DD; i += 256) {
        int k = i >> 7, d = i & 127;
        sW3[d * 72 + k] = __float2half(Wn3[i]);
    }
    if (t < HH) { b1[t] = bn1[t]; b2[t] = bn2[t]; }
    if (t < DD) b3[t] = bn3[t];
    __syncthreads();

    const int lane = t & 31, wid = t >> 5;
    const int g = lane >> 2, tig = lane & 3;
    __half* stage = (__half*)(sm + N_STG) + wid * (16 * 136);
    const int srow = lane >> 1, shalf = lane & 1;

    const int nunits = (NN + 15) >> 4;
    const int slot0 = blockIdx.x * 8 + wid;
    const int nslots = gridDim.x * 8;

    for (int u = slot0; u < nunits; u += nslots) {
        const int base = u * 16;
        // stage relu(x)
        {
            int n = base + srow;
            __half* dr = stage + srow * 136 + shalf * 64;
            if (n < NN) {
                const float* xr = nf + (long)n * DD + shalf * 64;
                #pragma unroll
                for (int i = 0; i < 16; i++) {
                    float4 v = *(const float4*)(xr + 4 * i);
                    uint2 hp;
                    hp.x = pack_h2(fmaxf(v.x, 0.f), fmaxf(v.y, 0.f));
                    hp.y = pack_h2(fmaxf(v.z, 0.f), fmaxf(v.w, 0.f));
                    *(uint2*)(dr + 4 * i) = hp;
                }
            } else {
                #pragma unroll
                for (int i = 0; i < 16; i++)
                    *(uint2*)(dr + 4 * i) = make_uint2(0u, 0u);
            }
        }
        __syncwarp();

        const int n0 = base + g, n1 = base + g + 8;

        // L1: K=128, N=64
        float c1[8][4] = {};
        #pragma unroll
        for (int kb = 0; kb < 8; kb++) {
            const __half* ar = stage + g * 136 + kb * 16 + 2 * tig;
            uint32_t a0 = *(const uint32_t*)ar;
            uint32_t a1 = *(const uint32_t*)(ar + 8 * 136);
            uint32_t a2 = *(const uint32_t*)(ar + 8);
            uint32_t a3 = *(const uint32_t*)(ar + 8 * 136 + 8);
            #pragma unroll
            for (int j = 0; j < 8; j++) {
                const __half* wn = sW1 + (8 * j + g) * 136 + kb * 16 + 2 * tig;
                mma_f16(c1[j], a0, a1, a2, a3,
                        *(const uint32_t*)wn, *(const uint32_t*)(wn + 8));
            }
        }
        // epilogue: + g_acc + bias, relu, repack to A
        uint32_t A[8][4];
        #pragma unroll
        for (int kb = 0; kb < 4; kb++) {
            int j0 = 2 * kb, j1 = j0 + 1;
            int col0 = 8 * j0 + 2 * tig, col1 = 8 * j1 + 2 * tig;
            float2 bb0 = *(const float2*)(b1 + col0);
            float2 bb1 = *(const float2*)(b1 + col1);
            float2 z = make_float2(0.f, 0.f);
            float2 ga00 = (n0 < NN) ? *(const float2*)(g_acc + (long)n0 * HH + col0) : z;
            float2 ga01 = (n0 < NN) ? *(const float2*)(g_acc + (long)n0 * HH + col1) : z;
            float2 ga10 = (n1 < NN) ? *(const float2*)(g_acc + (long)n1 * HH + col0) : z;
            float2 ga11 = (n1 < NN) ? *(const float2*)(g_acc + (long)n1 * HH + col1) : z;
            A[kb][0] = pack_h2(fmaxf(c1[j0][0] + ga00.x + bb0.x, 0.f),
                               fmaxf(c1[j0][1] + ga00.y + bb0.y, 0.f));
            A[kb][1] = pack_h2(fmaxf(c1[j0][2] + ga10.x + bb0.x, 0.f),
                               fmaxf(c1[j0][3] + ga10.y + bb0.y, 0.f));
            A[kb][2] = pack_h2(fmaxf(c1[j1][0] + ga01.x + bb1.x, 0.f),
                               fmaxf(c1[j1][1] + ga01.y + bb1.y, 0.f));
            A[kb][3] = pack_h2(fmaxf(c1[j1][2] + ga11.x + bb1.x, 0.f),
                               fmaxf(c1[j1][3] + ga11.y + bb1.y, 0.f));
        }

        // L2
        float c2[8][4] = {};
        do_layer<4, 8, 72>(A, sW2, g, tig, c2);
        cvt_relu<4>(c2, b2, tig, A);

        // L3: K=64, N=128 -> out (f32)
        float c3[16][4] = {};
        do_layer<4, 16, 72>(A, sW3, g, tig, c3);
        #pragma unroll
        for (int j = 0; j < 16; j++) {
            int col = 8 * j + 2 * tig;
            float2 bb = *(const float2*)(b3 + col);
            if (n0 < NN) {
                float2 v; v.x = c3[j][0] + bb.x; v.y = c3[j][1] + bb.y;
                *(float2*)(out + (long)n0 * DD + col) = v;
            }
            if (n1 < NN) {
                float2 v; v.x = c3[j][2] + bb.x; v.y = c3[j][3] + bb.y;
                *(float2*)(out + (long)n1 * DD + col) = v;
            }
        }
        __syncwarp();
    }
}

extern "C" void kernel_launch(void* const* d_in, const int* in_sizes, int n_in,
                              void* d_out, int out_size) {
    const float* nf   = (const float*)d_in[0];
    const int*   esrc = (const int*)d_in[1];
    const int*   edst = (const int*)d_in[2];
    const int*   etyp = (const int*)d_in[3];
    const float* Wr1  = (const float*)d_in[4];
    const float* br1  = (const float*)d_in[5];
    const float* Wr2  = (const float*)d_in[6];
    const float* br2  = (const float*)d_in[7];
    const float* Wr3  = (const float*)d_in[8];
    const float* br3  = (const float*)d_in[9];
    const float* Wn1  = (const float*)d_in[10];
    const float* bn1  = (const float*)d_in[11];
    const float* Wn2  = (const float*)d_in[12];
    const float* bn2  = (const float*)d_in[13];
    const float* Wn3  = (const float*)d_in[14];
    const float* bn3  = (const float*)d_in[15];
    float* out = (float*)d_out;

    cudaFuncSetAttribute(edge_kernel, cudaFuncAttributeMaxDynamicSharedMemorySize, E_TOT);
    cudaFuncSetAttribute(node_kernel, cudaFuncAttributeMaxDynamicSharedMemorySize, N_TOT);

    void* accp = nullptr; void* cntp = nullptr;
    cudaGetSymbolAddress(&accp, g_acc);
    cudaGetSymbolAddress(&cntp, g_cnt);
    cudaMemsetAsync(accp, 0, (size_t)NN * HH * sizeof(float));
    cudaMemsetAsync(cntp, 0, RR * sizeof(int));

    bin_kernel<<<(NE + 255) / 256, 256>>>(etyp);
    edge_kernel<<<NSM, 256, E_TOT>>>(nf, esrc, edst,
                                     Wr1, br1, Wr2, br2, Wr3, br3, Wn1);
    node_kernel<<<NSM, 256, N_TOT>>>(nf, Wn1, bn1, Wn2, bn2, Wn3, bn3, out);
}

// round 10
// speedup vs baseline: 1.0212x; 1.0212x over previous
#include <cuda_runtime.h>
#include <cuda_fp16.h>
#include <cstdint>

#define NN 50000
#define NE 200000
#define DD 128
#define RR 4
#define HH 64
#define NSM 152

__device__ float g_acc[NN * HH];
__device__ int   g_bucket[RR * NE];
__device__ int   g_cnt[RR];

__global__ void bin_kernel(const int* __restrict__ etype) {
    __shared__ int s_cnt[RR];
    __shared__ int s_base[RR];
    int t = threadIdx.x;
    if (t < RR) s_cnt[t] = 0;
    __syncthreads();
    int e = blockIdx.x * blockDim.x + t;
    int r = -1, pos = 0;
    if (e < NE) { r = etype[e]; pos = atomicAdd(&s_cnt[r], 1); }
    __syncthreads();
    if (t < RR) s_base[t] = atomicAdd(&g_cnt[t], s_cnt[t]);
    __syncthreads();
    if (r >= 0) g_bucket[r * NE + s_base[r] + pos] = e;
}

// ---- helpers ----------------------------------------------------------------
__device__ __forceinline__ void mma_f16(float c[4], uint32_t a0, uint32_t a1,
                                        uint32_t a2, uint32_t a3,
                                        uint32_t b0, uint32_t b1) {
    asm volatile(
        "mma.sync.aligned.m16n8k16.row.col.f32.f16.f16.f32 "
        "{%0,%1,%2,%3}, {%4,%5,%6,%7}, {%8,%9}, {%0,%1,%2,%3};"
        : "+f"(c[0]), "+f"(c[1]), "+f"(c[2]), "+f"(c[3])
        : "r"(a0), "r"(a1), "r"(a2), "r"(a3), "r"(b0), "r"(b1));
}
__device__ __forceinline__ uint32_t pack_h2(float lo, float hi) {
    uint32_t r;
    asm("cvt.rn.f16x2.f32 %0, %1, %2;" : "=r"(r) : "f"(hi), "f"(lo));
    return r;
}
__device__ __forceinline__ void red2(float* p, float x, float y) {
    asm volatile("red.global.add.v2.f32 [%0], {%1, %2};"
                 :: "l"(p), "f"(x), "f"(y) : "memory");
}

// Layer GEMM on register A fragments. A[kb][4] covers k = 16kb..16kb+15 for the
// warp's 16 rows; wT is [N][KS] f16 (K contiguous); C chunks j cover cols 8j..8j+7.
template<int KB, int NCH, int KS>
__device__ __forceinline__ void do_layer(const uint32_t A[][4],
                                         const __half* __restrict__ wT,
                                         int g, int tig, float c[][4]) {
    #pragma unroll
    for (int kb = 0; kb < KB; kb++) {
        #pragma unroll
        for (int j = 0; j < NCH; j++) {
            const __half* wn = wT + (8 * j + g) * KS + kb * 16 + 2 * tig;
            mma_f16(c[j], A[kb][0], A[kb][1], A[kb][2], A[kb][3],
                    *(const uint32_t*)wn, *(const uint32_t*)(wn + 8));
        }
    }
}

// bias + relu + repack C chunks (2 per k-block) into next-layer A fragments.
template<int KB2>
__device__ __forceinline__ void cvt_relu(const float c[][4],
                                         const float* __restrict__ bias,
                                         int tig, uint32_t A[][4]) {
    #pragma unroll
    for (int kb = 0; kb < KB2; kb++) {
        int j0 = 2 * kb, j1 = j0 + 1;
        float2 b0 = *(const float2*)(bias + 8 * j0 + 2 * tig);
        float2 b1 = *(const float2*)(bias + 8 * j1 + 2 * tig);
        A[kb][0] = pack_h2(fmaxf(c[j0][0] + b0.x, 0.f), fmaxf(c[j0][1] + b0.y, 0.f));
        A[kb][1] = pack_h2(fmaxf(c[j0][2] + b0.x, 0.f), fmaxf(c[j0][3] + b0.y, 0.f));
        A[kb][2] = pack_h2(fmaxf(c[j1][0] + b1.x, 0.f), fmaxf(c[j1][1] + b1.y, 0.f));
        A[kb][3] = pack_h2(fmaxf(c[j1][2] + b1.x, 0.f), fmaxf(c[j1][3] + b1.y, 0.f));
    }
}

// SMEM layouts (byte offsets). Weight rows stride: 136 halves (K=128), 72 (K=64)
// -> B-fragment LDS conflict-free.
#define E_W1 0
#define E_W2 17408
#define E_W3 26624
#define E_WN 45056
#define E_B1 62464
#define E_B2 62720
#define E_B3 62976
#define E_STG 63488        /* 8 warps x 16 rows x 136 halves */
#define E_TOT 98304        /* x2 = 196.6 KB <= 228 KB -> occ 2 */

#define N_W1 0
#define N_W2 17408
#define N_W3 26624
#define N_B1 45056
#define N_B2 45312
#define N_B3 45568
#define N_STG 46080
#define N_TOT 80896        /* x2 fits */

// ---------------------------------------------------------------------------
// Edge kernel: each WARP independently processes 16 edges through all 4 layers;
// activations live in registers between layers. 2 CTAs/SM for latency hiding.
// ---------------------------------------------------------------------------
__global__ __launch_bounds__(256, 2)
void edge_kernel(const float* __restrict__ nf,
                 const int* __restrict__ esrc, const int* __restrict__ edst,
                 const float* __restrict__ Wr1, const float* __restrict__ br1,
                 const float* __restrict__ Wr2, const float* __restrict__ br2,
                 const float* __restrict__ Wr3, const float* __restrict__ br3,
                 const float* __restrict__ Wn1) {
    extern __shared__ __align__(16) char sm[];
    __half* sW1 = (__half*)(sm + E_W1);   // [64][136]  W1^T
    __half* sW2 = (__half*)(sm + E_W2);   // [64][72]
    __half* sW3 = (__half*)(sm + E_W3);   // [128][72]
    __half* sWn = (__half*)(sm + E_WN);   // [64][136]
    float*  b1  = (float*)(sm + E_B1);
    float*  b2  = (float*)(sm + E_B2);
    float*  b3  = (float*)(sm + E_B3);

    const int t = threadIdx.x;
    const int rel = blockIdx.x & (RR - 1);

    const float* gW1 = Wr1 + rel * DD * HH;
    const float* gW2 = Wr2 + rel * HH * HH;
    const float* gW3 = Wr3 + rel * HH * DD;
    const float* gWn = Wn1 + (1 + rel) * DD * HH;
    for (int i = t; i < DD * HH; i += 256) {
        int d = i >> 6, h = i & 63;
        sW1[h * 136 + d] = __float2half(gW1[i]);
        sWn[h * 136 + d] = __float2half(gWn[i]);
    }
    for (int i = t; i < HH * HH; i += 256) {
        int k = i >> 6, h = i & 63;
        sW2[h * 72 + k] = __float2half(gW2[i]);
    }
    for (int i = t; i < HH * DD; i += 256) {
        int k = i >> 7, d = i & 127;
        sW3[d * 72 + k] = __float2half(gW3[i]);
    }
    if (t < HH) { b1[t] = br1[rel * HH + t]; b2[t] = br2[rel * HH + t]; }
    if (t < DD) { b3[t] = br3[rel * DD + t]; }
    __syncthreads();

    const int lane = t & 31, wid = t >> 5;
    const int g = lane >> 2, tig = lane & 3;
    __half* stage = (__half*)(sm + E_STG) + wid * (16 * 136);
    const int srow = lane >> 1, shalf = lane & 1;    // 2 lanes gather one row

    const int cnt = g_cnt[rel];
    const int nunits = (cnt + 15) >> 4;
    const int slot0 = (blockIdx.x >> 2) * 8 + wid;
    const int nslots = (gridDim.x >> 2) * 8;

    for (int u = slot0; u < nunits; u += nslots) {
        int s = 0, d = -1;
        if (lane < 16) {
            int idx = u * 16 + lane;
            if (idx < cnt) {
                int e = g_bucket[rel * NE + idx];
                s = esrc[e]; d = edst[e];
            }
        }
        int src_r = __shfl_sync(0xffffffffu, s, srow);
        int d0 = __shfl_sync(0xffffffffu, d, g);
        int d1 = __shfl_sync(0xffffffffu, d, g + 8);

        // stage x_src[16 rows][128] as f16
        {
            const float* xr = nf + (long)src_r * DD + shalf * 64;
            __half* dr = stage + srow * 136 + shalf * 64;
            #pragma unroll
            for (int i = 0; i < 16; i++) {
                float4 v = *(const float4*)(xr + 4 * i);
                uint2 hp; hp.x = pack_h2(v.x, v.y); hp.y = pack_h2(v.z, v.w);
                *(uint2*)(dr + 4 * i) = hp;
            }
        }
        __syncwarp();

        // L1: K=128, N=64 (A from staged x)
        float c1[8][4] = {};
        #pragma unroll
        for (int kb = 0; kb < 8; kb++) {
            const __half* ar = stage + g * 136 + kb * 16 + 2 * tig;
            uint32_t a0 = *(const uint32_t*)ar;
            uint32_t a1 = *(const uint32_t*)(ar + 8 * 136);
            uint32_t a2 = *(const uint32_t*)(ar + 8);
            uint32_t a3 = *(const uint32_t*)(ar + 8 * 136 + 8);
            #pragma unroll
            for (int j = 0; j < 8; j++) {
                const __half* wn = sW1 + (8 * j + g) * 136 + kb * 16 + 2 * tig;
                mma_f16(c1[j], a0, a1, a2, a3,
                        *(const uint32_t*)wn, *(const uint32_t*)(wn + 8));
            }
        }
        uint32_t A[8][4];
        cvt_relu<4>(c1, b1, tig, A);

        // L2: K=64, N=64
        float c2[8][4] = {};
        do_layer<4, 8, 72>(A, sW2, g, tig, c2);
        cvt_relu<4>(c2, b2, tig, A);

        // L3: K=64, N=128 — split into two N=64 halves to cap register peak
        uint32_t A2[8][4];
        {
            float c3[8][4] = {};
            do_layer<4, 8, 72>(A, sW3, g, tig, c3);          // cols 0..63
            cvt_relu<4>(c3, b3, tig, A2);
        }
        {
            float c3[8][4] = {};
            do_layer<4, 8, 72>(A, sW3 + 64 * 72, g, tig, c3); // cols 64..127
            cvt_relu<4>(c3, b3 + 64, tig, A2 + 4);
        }

        // L4: K=128, N=64 (fused node-layer-1 projection)
        float c4[8][4] = {};
        do_layer<8, 8, 136>(A2, sWn, g, tig, c4);

        #pragma unroll
        for (int j = 0; j < 8; j++) {
            int col = 8 * j + 2 * tig;
            if (d0 >= 0) red2(g_acc + (long)d0 * HH + col, c4[j][0], c4[j][1]);
            if (d1 >= 0) red2(g_acc + (long)d1 * HH + col, c4[j][2], c4[j][3]);
        }
        __syncwarp();   // staging reuse
    }
}

// ---------------------------------------------------------------------------
// Node kernel: warp-independent 16-node units; g_acc fused into L1 epilogue.
// ---------------------------------------------------------------------------
__global__ __launch_bounds__(256, 2)
void node_kernel(const float* __restrict__ nf,
                 const float* __restrict__ Wn1, const float* __restrict__ bn1,
                 const float* __restrict__ Wn2, const float* __restrict__ bn2,
                 const float* __restrict__ Wn3, const float* __restrict__ bn3,
                 float* __restrict__ out) {
    extern __shared__ __align__(16) char sm[];
    __half* sW1 = (__half*)(sm + N_W1);
    __half* sW2 = (__half*)(sm + N_W2);
    __half* sW3 = (__half*)(sm + N_W3);
    float*  b1  = (float*)(sm + N_B1);
    float*  b2  = (float*)(sm + N_B2);
    float*  b3  = (float*)(sm + N_B3);

    const int t = threadIdx.x;
    for (int i = t; i < DD * HH; i += 256) {
        int d = i >> 6, h = i & 63;
        sW1[h * 136 + d] = __float2half(Wn1[i]);
    }
    for (int i = t; i < HH * HH; i += 256) {
        int k = i >> 6, h = i & 63;
        sW2[h * 72 + k] = __float2half(Wn2[i]);
    }
    for (int i = t; i < HH * DD; i += 256) {
        int k = i >> 7, d = i & 127;
        sW3[d * 72 + k] = __float2half(Wn3[i]);
    }
    if (t < HH) { b1[t] = bn1[t]; b2[t] = bn2[t]; }
    if (t < DD) b3[t] = bn3[t];
    __syncthreads();

    const int lane = t & 31, wid = t >> 5;
    const int g = lane >> 2, tig = lane & 3;
    __half* stage = (__half*)(sm + N_STG) + wid * (16 * 136);
    const int srow = lane >> 1, shalf = lane & 1;

    const int nunits = (NN + 15) >> 4;
    const int slot0 = blockIdx.x * 8 + wid;
    const int nslots = gridDim.x * 8;

    for (int u = slot0; u < nunits; u += nslots) {
        const int base = u * 16;
        // stage relu(x)
        {
            int n = base + srow;
            __half* dr = stage + srow * 136 + shalf * 64;
            if (n < NN) {
                const float* xr = nf + (long)n * DD + shalf * 64;
                #pragma unroll
                for (int i = 0; i < 16; i++) {
                    float4 v = *(const float4*)(xr + 4 * i);
                    uint2 hp;
                    hp.x = pack_h2(fmaxf(v.x, 0.f), fmaxf(v.y, 0.f));
                    hp.y = pack_h2(fmaxf(v.z, 0.f), fmaxf(v.w, 0.f));
                    *(uint2*)(dr + 4 * i) = hp;
                }
            } else {
                #pragma unroll
                for (int i = 0; i < 16; i++)
                    *(uint2*)(dr + 4 * i) = make_uint2(0u, 0u);
            }
        }
        __syncwarp();

        const int n0 = base + g, n1 = base + g + 8;

        // L1: K=128, N=64
        float c1[8][4] = {};
        #pragma unroll
        for (int kb = 0; kb < 8; kb++) {
            const __half* ar = stage + g * 136 + kb * 16 + 2 * tig;
            uint32_t a0 = *(const uint32_t*)ar;
            uint32_t a1 = *(const uint32_t*)(ar + 8 * 136);
            uint32_t a2 = *(const uint32_t*)(ar + 8);
            uint32_t a3 = *(const uint32_t*)(ar + 8 * 136 + 8);
            #pragma unroll
            for (int j = 0; j < 8; j++) {
                const __half* wn = sW1 + (8 * j + g) * 136 + kb * 16 + 2 * tig;
                mma_f16(c1[j], a0, a1, a2, a3,
                        *(const uint32_t*)wn, *(const uint32_t*)(wn + 8));
            }
        }
        // epilogue: + g_acc + bias, relu, repack to A
        uint32_t A[8][4];
        #pragma unroll
        for (int kb = 0; kb < 4; kb++) {
            int j0 = 2 * kb, j1 = j0 + 1;
            int col0 = 8 * j0 + 2 * tig, col1 = 8 * j1 + 2 * tig;
            float2 bb0 = *(const float2*)(b1 + col0);
            float2 bb1 = *(const float2*)(b1 + col1);
            float2 z = make_float2(0.f, 0.f);
            float2 ga00 = (n0 < NN) ? *(const float2*)(g_acc + (long)n0 * HH + col0) : z;
            float2 ga01 = (n0 < NN) ? *(const float2*)(g_acc + (long)n0 * HH + col1) : z;
            float2 ga10 = (n1 < NN) ? *(const float2*)(g_acc + (long)n1 * HH + col0) : z;
            float2 ga11 = (n1 < NN) ? *(const float2*)(g_acc + (long)n1 * HH + col1) : z;
            A[kb][0] = pack_h2(fmaxf(c1[j0][0] + ga00.x + bb0.x, 0.f),
                               fmaxf(c1[j0][1] + ga00.y + bb0.y, 0.f));
            A[kb][1] = pack_h2(fmaxf(c1[j0][2] + ga10.x + bb0.x, 0.f),
                               fmaxf(c1[j0][3] + ga10.y + bb0.y, 0.f));
            A[kb][2] = pack_h2(fmaxf(c1[j1][0] + ga01.x + bb1.x, 0.f),
                               fmaxf(c1[j1][1] + ga01.y + bb1.y, 0.f));
            A[kb][3] = pack_h2(fmaxf(c1[j1][2] + ga11.x + bb1.x, 0.f),
                               fmaxf(c1[j1][3] + ga11.y + bb1.y, 0.f));
        }

        // L2
        float c2[8][4] = {};
        do_layer<4, 8, 72>(A, sW2, g, tig, c2);
        cvt_relu<4>(c2, b2, tig, A);

        // L3: K=64, N=128 -> out (f32), two N=64 halves
        #pragma unroll
        for (int h = 0; h < 2; h++) {
            float c3[8][4] = {};
            do_layer<4, 8, 72>(A, sW3 + h * 64 * 72, g, tig, c3);
            #pragma unroll
            for (int j = 0; j < 8; j++) {
                int col = h * 64 + 8 * j + 2 * tig;
                float2 bb = *(const float2*)(b3 + col);
                if (n0 < NN) {
                    float2 v; v.x = c3[j][0] + bb.x; v.y = c3[j][1] + bb.y;
                    *(float2*)(out + (long)n0 * DD + col) = v;
                }
                if (n1 < NN) {
                    float2 v; v.x = c3[j][2] + bb.x; v.y = c3[j][3] + bb.y;
                    *(float2*)(out + (long)n1 * DD + col) = v;
                }
            }
        }
        __syncwarp();
    }
}

extern "C" void kernel_launch(void* const* d_in, const int* in_sizes, int n_in,
                              void* d_out, int out_size) {
    const float* nf   = (const float*)d_in[0];
    const int*   esrc = (const int*)d_in[1];
    const int*   edst = (const int*)d_in[2];
    const int*   etyp = (const int*)d_in[3];
    const float* Wr1  = (const float*)d_in[4];
    const float* br1  = (const float*)d_in[5];
    const float* Wr2  = (const float*)d_in[6];
    const float* br2  = (const float*)d_in[7];
    const float* Wr3  = (const float*)d_in[8];
    const float* br3  = (const float*)d_in[9];
    const float* Wn1  = (const float*)d_in[10];
    const float* bn1  = (const float*)d_in[11];
    const float* Wn2  = (const float*)d_in[12];
    const float* bn2  = (const float*)d_in[13];
    const float* Wn3  = (const float*)d_in[14];
    const float* bn3  = (const float*)d_in[15];
    float* out = (float*)d_out;

    cudaFuncSetAttribute(edge_kernel, cudaFuncAttributeMaxDynamicSharedMemorySize, E_TOT);
    cudaFuncSetAttribute(node_kernel, cudaFuncAttributeMaxDynamicSharedMemorySize, N_TOT);

    void* accp = nullptr; void* cntp = nullptr;
    cudaGetSymbolAddress(&accp, g_acc);
    cudaGetSymbolAddress(&cntp, g_cnt);
    cudaMemsetAsync(accp, 0, (size_t)NN * HH * sizeof(float));
    cudaMemsetAsync(cntp, 0, RR * sizeof(int));

    bin_kernel<<<(NE + 255) / 256, 256>>>(etyp);
    edge_kernel<<<2 * NSM, 256, E_TOT>>>(nf, esrc, edst,
                                         Wr1, br1, Wr2, br2, Wr3, br3, Wn1);
    node_kernel<<<2 * NSM, 256, N_TOT>>>(nf, Wn1, bn1, Wn2, bn2, Wn3, bn3, out);
}

// round 11
// speedup vs baseline: 1.0519x; 1.0301x over previous
#include <cuda_runtime.h>
#include <cuda_fp16.h>
#include <cstdint>

#define NN 50000
#define NE 200000
#define DD 128
#define RR 4
#define HH 64
#define TE 64            // rows (edges/nodes) per tile (M)
#define XSH 136          // stride (halves) for 128-wide buffers; /2 = 68 ≡ 4 mod 32
#define HSH 72           // stride (halves) for 64-wide buffers;   /2 = 36 ≡ 4 mod 32
#define NTHREADS 256
#define NSM 152

__device__ float g_acc[NN * HH];
__device__ int   g_bucket[RR * NE];
__device__ int   g_cnt[RR];

__global__ void bin_kernel(const int* __restrict__ etype) {
    __shared__ int s_cnt[RR];
    __shared__ int s_base[RR];
    int t = threadIdx.x;
    if (t < RR) s_cnt[t] = 0;
    __syncthreads();
    int e = blockIdx.x * blockDim.x + t;
    int r = -1, pos = 0;
    if (e < NE) { r = etype[e]; pos = atomicAdd(&s_cnt[r], 1); }
    __syncthreads();
    if (t < RR) s_base[t] = atomicAdd(&g_cnt[t], s_cnt[t]);
    __syncthreads();
    if (r >= 0) g_bucket[r * NE + s_base[r] + pos] = e;
}

// ---- fp16 MMA helpers -------------------------------------------------------
__device__ __forceinline__ void mma_f16(float c[4], uint32_t a0, uint32_t a1,
                                        uint32_t a2, uint32_t a3,
                                        uint32_t b0, uint32_t b1) {
    asm volatile(
        "mma.sync.aligned.m16n8k16.row.col.f32.f16.f16.f32 "
        "{%0,%1,%2,%3}, {%4,%5,%6,%7}, {%8,%9}, {%0,%1,%2,%3};"
        : "+f"(c[0]), "+f"(c[1]), "+f"(c[2]), "+f"(c[3])
        : "r"(a0), "r"(a1), "r"(a2), "r"(a3), "r"(b0), "r"(b1));
}
__device__ __forceinline__ void red4(float* p, float a, float b, float c, float d) {
    asm volatile("red.global.add.v4.f32 [%0], {%1,%2,%3,%4};"
                 :: "l"(p), "f"(a), "f"(b), "f"(c), "f"(d) : "memory");
}

// Warp GEMM over K (fp16 in, fp32 acc). act: [M][AST] halves, wT: [N][KS] halves.
// Warp covers rows mrow0..+15, cols ncol0..+8*NCH-1.
// C frag: c[j][0]=[g][col], c[j][1]=[g][col+1], c[j][2]=[g+8][col], c[j][3]=[g+8][col+1],
// col = ncol0 + j*8 + 2*tig.
template<int K, int AST, int KS, int NCH>
__device__ __forceinline__ void wgemm(const __half* __restrict__ act,
                                      const __half* __restrict__ wT,
                                      int mrow0, int ncol0, int g, int tig,
                                      float c[NCH][4]) {
    const __half* ar0 = act + (mrow0 + g) * AST + 2 * tig;
    const __half* ar1 = ar0 + 8 * AST;
    #pragma unroll
    for (int k0 = 0; k0 < K; k0 += 16) {
        uint32_t a0 = *(const uint32_t*)(ar0 + k0);
        uint32_t a1 = *(const uint32_t*)(ar1 + k0);
        uint32_t a2 = *(const uint32_t*)(ar0 + k0 + 8);
        uint32_t a3 = *(const uint32_t*)(ar1 + k0 + 8);
        #pragma unroll
        for (int j = 0; j < NCH; j++) {
            const __half* wn = wT + (ncol0 + j * 8 + g) * KS + k0 + 2 * tig;
            uint32_t b0 = *(const uint32_t*)(wn);
            uint32_t b1 = *(const uint32_t*)(wn + 8);
            mma_f16(c[j], a0, a1, a2, a3, b0, b1);
        }
    }
}

// Epilogue: bias + relu + fp16-round, store half2 to smem [M][OST].
template<int NCH>
__device__ __forceinline__ void epi_store(float c[NCH][4], __half* outb, int OST,
                                          const float* bias, int mrow0, int ncol0,
                                          int g, int tig) {
    #pragma unroll
    for (int j = 0; j < NCH; j++) {
        int col = ncol0 + j * 8 + 2 * tig;
        float b0 = bias[col], b1 = bias[col + 1];
        *(half2*)(outb + (mrow0 + g) * OST + col) =
            __floats2half2_rn(fmaxf(c[j][0] + b0, 0.f), fmaxf(c[j][1] + b1, 0.f));
        *(half2*)(outb + (mrow0 + g + 8) * OST + col) =
            __floats2half2_rn(fmaxf(c[j][2] + b0, 0.f), fmaxf(c[j][3] + b1, 0.f));
    }
}

// SMEM layouts (byte offsets)
#define E_W1T 0
#define E_W2T (E_W1T + HH * XSH * 2)
#define E_W3T (E_W2T + HH * HSH * 2)
#define E_WNT (E_W3T + DD * HSH * 2)
#define E_SX  (E_WNT + HH * XSH * 2)
#define E_SH1 (E_SX + TE * XSH * 2)
#define E_SH2 (E_SH1 + TE * HSH * 2)
#define E_SB1 (E_SH2 + TE * HSH * 2)
#define E_SB2 (E_SB1 + HH * 4)
#define E_SB3 (E_SB2 + HH * 4)
#define E_SRC (E_SB3 + DD * 4)
#define E_DST (E_SRC + TE * 4)
#define E_TOTAL (E_DST + TE * 4)          // 99840 B -> occ 2

#define N_W1T 0
#define N_W2T (N_W1T + HH * XSH * 2)
#define N_W3T (N_W2T + HH * HSH * 2)
#define N_SX  (N_W3T + DD * HSH * 2)
#define N_SH1 (N_SX + TE * XSH * 2)
#define N_SH2 (N_SH1 + TE * HSH * 2)
#define N_SB1 (N_SH2 + TE * HSH * 2)
#define N_SB2 (N_SB1 + HH * 4)
#define N_SB3 (N_SB2 + HH * 4)
#define N_TOTAL (N_SB3 + DD * 4)          // 81920 B -> occ 2

// ---------------------------------------------------------------------------
// Edge kernel: per edge of relation r:
//   h1=relu(x@W1+b1); h2=relu(h1@W2+b2); msg=relu(h2@W3+b3);
//   p=msg@Wn1[(1+r)D:(2+r)D];  g_acc[dst] += p  (red.v4 via pair-shuffle)
// ---------------------------------------------------------------------------
__global__ __launch_bounds__(NTHREADS, 2)
void edge_kernel(const float* __restrict__ nf,
                 const int* __restrict__ esrc, const int* __restrict__ edst,
                 const float* __restrict__ Wr1, const float* __restrict__ br1,
                 const float* __restrict__ Wr2, const float* __restrict__ br2,
                 const float* __restrict__ Wr3, const float* __restrict__ br3,
                 const float* __restrict__ Wn1) {
    extern __shared__ __align__(16) char smraw[];
    __half* sW1T = (__half*)(smraw + E_W1T);   // [64][XSH]  W1^T
    __half* sW2T = (__half*)(smraw + E_W2T);   // [64][HSH]
    __half* sW3T = (__half*)(smraw + E_W3T);   // [128][HSH]
    __half* sWnT = (__half*)(smraw + E_WNT);   // [64][XSH]
    __half* sX   = (__half*)(smraw + E_SX);    // [64][XSH]  x / msg
    __half* sH1  = (__half*)(smraw + E_SH1);   // [64][HSH]
    __half* sH2  = (__half*)(smraw + E_SH2);   // [64][HSH]
    float*  sb1  = (float*)(smraw + E_SB1);
    float*  sb2  = (float*)(smraw + E_SB2);
    float*  sb3  = (float*)(smraw + E_SB3);
    int*    sSrc = (int*)(smraw + E_SRC);
    int*    sDst = (int*)(smraw + E_DST);

    const int t     = threadIdx.x;
    const int rel   = blockIdx.x & (RR - 1);
    const int bslot = blockIdx.x >> 2;
    const int nb    = gridDim.x >> 2;

    const float* gW1 = Wr1 + rel * DD * HH;
    const float* gW2 = Wr2 + rel * HH * HH;
    const float* gW3 = Wr3 + rel * HH * DD;
    const float* gWn = Wn1 + (1 + rel) * DD * HH;
    for (int i = t; i < DD * HH; i += NTHREADS) {
        int d = i >> 6, h = i & 63;
        sW1T[h * XSH + d] = __float2half(gW1[i]);
        sWnT[h * XSH + d] = __float2half(gWn[i]);
    }
    for (int i = t; i < HH * HH; i += NTHREADS) {
        int k = i >> 6, h = i & 63;
        sW2T[h * HSH + k] = __float2half(gW2[i]);
    }
    for (int i = t; i < HH * DD; i += NTHREADS) {
        int k = i >> 7, d = i & 127;
        sW3T[d * HSH + k] = __float2half(gW3[i]);
    }
    if (t < HH) { sb1[t] = br1[rel * HH + t]; sb2[t] = br2[rel * HH + t]; }
    if (t < DD) { sb3[t] = br3[rel * DD + t]; }

    const int cnt    = g_cnt[rel];
    const int ntiles = (cnt + TE - 1) / TE;

    const int lane = t & 31, w = t >> 5;
    const int g = lane >> 2, tig = lane & 3;
    const int mrow = (w & 3) * 16;
    const int nc4  = (w >> 2) * 32;
    const int nc8  = (w >> 2) * 64;
    const int grow = t >> 2, gj = t & 3;

    for (int tile = bslot; tile < ntiles; tile += nb) {
        __syncthreads();
        if (t < TE) {
            int idx = tile * TE + t;
            if (idx < cnt) {
                int e = g_bucket[rel * NE + idx];
                sSrc[t] = esrc[e];
                sDst[t] = edst[e];
            } else { sSrc[t] = 0; sDst[t] = -1; }
        }
        __syncthreads();

        // Gather x_src tile -> fp16
        {
            const float* xr = nf + (long)sSrc[grow] * DD;
            __half* dr = sX + grow * XSH;
            #pragma unroll
            for (int i = 0; i < 8; i++) {
                int d0 = gj * 4 + i * 16;
                float4 v = *(const float4*)(xr + d0);
                *(half2*)(dr + d0)     = __floats2half2_rn(v.x, v.y);
                *(half2*)(dr + d0 + 2) = __floats2half2_rn(v.z, v.w);
            }
        }
        __syncthreads();

        // L1: [64,128]@[128,64]
        {
            float c[4][4] = {};
            wgemm<DD, XSH, XSH, 4>(sX, sW1T, mrow, nc4, g, tig, c);
            epi_store<4>(c, sH1, HSH, sb1, mrow, nc4, g, tig);
        }
        __syncthreads();

        // L2: [64,64]@[64,64]
        {
            float c[4][4] = {};
            wgemm<HH, HSH, HSH, 4>(sH1, sW2T, mrow, nc4, g, tig, c);
            epi_store<4>(c, sH2, HSH, sb2, mrow, nc4, g, tig);
        }
        __syncthreads();

        // L3: [64,64]@[64,128] -> msg into sX
        {
            float c[8][4] = {};
            wgemm<HH, HSH, HSH, 8>(sH2, sW3T, mrow, nc8, g, tig, c);
            epi_store<8>(c, sX, XSH, sb3, mrow, nc8, g, tig);
        }
        __syncthreads();

        // L4: [64,128]@[128,64] -> red.v4 reductions into g_acc.
        // Thread-pair (tig, tig^1) jointly owns 4 contiguous columns of rows
        // (mrow+g) and (mrow+g+8); shfl.xor assembles 16B vectors.
        {
            float c[4][4] = {};
            wgemm<DD, XSH, XSH, 4>(sX, sWnT, mrow, nc4, g, tig, c);
            int d0 = sDst[mrow + g];
            int d1 = sDst[mrow + g + 8];
            #pragma unroll
            for (int j = 0; j < 4; j++) {
                float sx0 = __shfl_xor_sync(0xffffffffu, c[j][0], 1);
                float sx1 = __shfl_xor_sync(0xffffffffu, c[j][1], 1);
                float sx2 = __shfl_xor_sync(0xffffffffu, c[j][2], 1);
                float sx3 = __shfl_xor_sync(0xffffffffu, c[j][3], 1);
                int col4 = nc4 + j * 8 + (tig & 2) * 2;
                if ((tig & 1) == 0) {
                    // row mrow+g, cols col4..col4+3 = [c0, c1, partner.c0, partner.c1]
                    if (d0 >= 0)
                        red4(g_acc + (long)d0 * HH + col4, c[j][0], c[j][1], sx0, sx1);
                } else {
                    // row mrow+g+8, cols col4..col4+3 = [partner.c2, partner.c3, c2, c3]
                    if (d1 >= 0)
                        red4(g_acc + (long)d1 * HH + col4, sx2, sx3, c[j][2], c[j][3]);
                }
            }
        }
    }
}

// ---------------------------------------------------------------------------
// Node kernel: h=relu(relu(nf)@Wn1[0:D]+g_acc+bn1); h=relu(h@Wn2+bn2);
//              out=h@Wn3+bn3
// ---------------------------------------------------------------------------
__global__ __launch_bounds__(NTHREADS, 2)
void node_kernel(const float* __restrict__ nf,
                 const float* __restrict__ Wn1, const float* __restrict__ bn1,
                 const float* __restrict__ Wn2, const float* __restrict__ bn2,
                 const float* __restrict__ Wn3, const float* __restrict__ bn3,
                 float* __restrict__ out) {
    extern __shared__ __align__(16) char smraw[];
    __half* sW1T = (__half*)(smraw + N_W1T);
    __half* sW2T = (__half*)(smraw + N_W2T);
    __half* sW3T = (__half*)(smraw + N_W3T);
    __half* sX   = (__half*)(smraw + N_SX);
    __half* sH1  = (__half*)(smraw + N_SH1);
    __half* sH2  = (__half*)(smraw + N_SH2);
    float*  sb1  = (float*)(smraw + N_SB1);
    float*  sb2  = (float*)(smraw + N_SB2);
    float*  sb3  = (float*)(smraw + N_SB3);

    const int t = threadIdx.x;
    for (int i = t; i < DD * HH; i += NTHREADS) {
        int d = i >> 6, h = i & 63;
        sW1T[h * XSH + d] = __float2half(Wn1[i]);
    }
    for (int i = t; i < HH * HH; i += NTHREADS) {
        int k = i >> 6, h = i & 63;
        sW2T[h * HSH + k] = __float2half(Wn2[i]);
    }
    for (int i = t; i < HH * DD; i += NTHREADS) {
        int k = i >> 7, d = i & 127;
        sW3T[d * HSH + k] = __float2half(Wn3[i]);
    }
    if (t < HH) { sb1[t] = bn1[t]; sb2[t] = bn2[t]; }
    if (t < DD) sb3[t] = bn3[t];

    const int ntiles = (NN + TE - 1) / TE;
    const int lane = t & 31, w = t >> 5;
    const int g = lane >> 2, tig = lane & 3;
    const int mrow = (w & 3) * 16;
    const int nc4  = (w >> 2) * 32;
    const int nc8  = (w >> 2) * 64;
    const int grow = t >> 2, gj = t & 3;

    for (int tile = blockIdx.x; tile < ntiles; tile += gridDim.x) {
        const int base = tile * TE;
        __syncthreads();
        {
            const int n = base + grow;
            __half* dr = sX + grow * XSH;
            if (n < NN) {
                const float* xr = nf + (long)n * DD;
                #pragma unroll
                for (int i = 0; i < 8; i++) {
                    int d0 = gj * 4 + i * 16;
                    float4 v = *(const float4*)(xr + d0);
                    *(half2*)(dr + d0) =
                        __floats2half2_rn(fmaxf(v.x, 0.f), fmaxf(v.y, 0.f));
                    *(half2*)(dr + d0 + 2) =
                        __floats2half2_rn(fmaxf(v.z, 0.f), fmaxf(v.w, 0.f));
                }
            } else {
                #pragma unroll
                for (int i = 0; i < 8; i++) {
                    int d0 = gj * 4 + i * 16;
                    *(half2*)(dr + d0)     = __floats2half2_rn(0.f, 0.f);
                    *(half2*)(dr + d0 + 2) = __floats2half2_rn(0.f, 0.f);
                }
            }
        }
        __syncthreads();

        // L1 + g_acc + bias
        {
            float c[4][4] = {};
            wgemm<DD, XSH, XSH, 4>(sX, sW1T, mrow, nc4, g, tig, c);
            int n0 = base + mrow + g;
            int n1 = n0 + 8;
            #pragma unroll
            for (int j = 0; j < 4; j++) {
                int col = nc4 + j * 8 + 2 * tig;
                float b0 = sb1[col], b1 = sb1[col + 1];
                __half* o0 = sH1 + (mrow + g) * HSH + col;
                __half* o1 = sH1 + (mrow + g + 8) * HSH + col;
                if (n0 < NN) {
                    float2 ga = *(const float2*)(g_acc + (long)n0 * HH + col);
                    *(half2*)o0 = __floats2half2_rn(
                        fmaxf(c[j][0] + ga.x + b0, 0.f),
                        fmaxf(c[j][1] + ga.y + b1, 0.f));
                } else *(half2*)o0 = __floats2half2_rn(0.f, 0.f);
                if (n1 < NN) {
                    float2 ga = *(const float2*)(g_acc + (long)n1 * HH + col);
                    *(half2*)o1 = __floats2half2_rn(
                        fmaxf(c[j][2] + ga.x + b0, 0.f),
                        fmaxf(c[j][3] + ga.y + b1, 0.f));
                } else *(half2*)o1 = __floats2half2_rn(0.f, 0.f);
            }
        }
        __syncthreads();

        // L2
        {
            float c[4][4] = {};
            wgemm<HH, HSH, HSH, 4>(sH1, sW2T, mrow, nc4, g, tig, c);
            epi_store<4>(c, sH2, HSH, sb2, mrow, nc4, g, tig);
        }
        __syncthreads();

        // L3 -> out (fp32)
        {
            float c[8][4] = {};
            wgemm<HH, HSH, HSH, 8>(sH2, sW3T, mrow, nc8, g, tig, c);
            int n0 = base + mrow + g;
            int n1 = n0 + 8;
            #pragma unroll
            for (int j = 0; j < 8; j++) {
                int col = nc8 + j * 8 + 2 * tig;
                float b0 = sb3[col], b1 = sb3[col + 1];
                if (n0 < NN) {
                    float2 v; v.x = c[j][0] + b0; v.y = c[j][1] + b1;
                    *(float2*)(out + (long)n0 * DD + col) = v;
                }
                if (n1 < NN) {
                    float2 v; v.x = c[j][2] + b0; v.y = c[j][3] + b1;
                    *(float2*)(out + (long)n1 * DD + col) = v;
                }
            }
        }
        __syncthreads();
    }
}

extern "C" void kernel_launch(void* const* d_in, const int* in_sizes, int n_in,
                              void* d_out, int out_size) {
    const float* nf   = (const float*)d_in[0];
    const int*   esrc = (const int*)d_in[1];
    const int*   edst = (const int*)d_in[2];
    const int*   etyp = (const int*)d_in[3];
    const float* Wr1  = (const float*)d_in[4];
    const float* br1  = (const float*)d_in[5];
    const float* Wr2  = (const float*)d_in[6];
    const float* br2  = (const float*)d_in[7];
    const float* Wr3  = (const float*)d_in[8];
    const float* br3  = (const float*)d_in[9];
    const float* Wn1  = (const float*)d_in[10];
    const float* bn1  = (const float*)d_in[11];
    const float* Wn2  = (const float*)d_in[12];
    const float* bn2  = (const float*)d_in[13];
    const float* Wn3  = (const float*)d_in[14];
    const float* bn3  = (const float*)d_in[15];
    float* out = (float*)d_out;

    cudaFuncSetAttribute(edge_kernel, cudaFuncAttributeMaxDynamicSharedMemorySize, E_TOTAL);
    cudaFuncSetAttribute(node_kernel, cudaFuncAttributeMaxDynamicSharedMemorySize, N_TOTAL);

    void* accp = nullptr; void* cntp = nullptr;
    cudaGetSymbolAddress(&accp, g_acc);
    cudaGetSymbolAddress(&cntp, g_cnt);
    cudaMemsetAsync(accp, 0, (size_t)NN * HH * sizeof(float));
    cudaMemsetAsync(cntp, 0, RR * sizeof(int));

    bin_kernel<<<(NE + NTHREADS - 1) / NTHREADS, NTHREADS>>>(etyp);
    edge_kernel<<<2 * NSM, NTHREADS, E_TOTAL>>>(nf, esrc, edst,
                                                Wr1, br1, Wr2, br2, Wr3, br3, Wn1);
    node_kernel<<<2 * NSM, NTHREADS, N_TOTAL>>>(nf, Wn1, bn1, Wn2, bn2, Wn3, bn3, out);
}